// round 12
// baseline (speedup 1.0000x reference)
#include <cuda_runtime.h>
#include <cuda_fp16.h>

// Problem constants
#define NB   2
#define GG   8
#define HW   2304     // 48*48
#define DD   2116     // 46*46
#define KROWS 2176    // DD padded to chunk multiple (17*128)
#define VROWS 2120    // DD padded for f16 16B alignment

// ---------------- scratch ----------------
__device__ __align__(256) __half g_xh16[NB][GG][HW][128];     // xh f16 [px][c]
__device__ __align__(256) __half g_in16[NB][HW][768];         // x_in+h f16 [px][c]
__device__ __align__(256) __half g_qt16[NB * GG * HW * 64];   // q [head][px][c] (tau*log2e folded)
__device__ __align__(256) __half g_kt16[NB * GG * KROWS * 64];// k [head][d][c]
__device__ __align__(256) __half g_vth[NB * GG * 64 * VROWS + 256]; // v [head][c][d]
__device__ __align__(256) __half g_at16[NB * GG * HW * 64];   // a [head][px][c]
__device__ __align__(256) __half g_gx16[4][NB * GG * HW * 64];// gate conv outs f16 [head][px][c]
__device__ __align__(256) __half g_wproj16[512 * 768];        // [co][ci]
__device__ __align__(256) __half g_wc16[7][GG][8][9][64][16]; // conv weights f16
__device__ __align__(256) __half g_wa16[4 * GG * 64 * 64];    // [gate][g][co][ci]

// ---------------- asm helpers ----------------
__device__ __forceinline__ void mma_f16(float* d, const unsigned* a, unsigned b0, unsigned b1) {
    asm volatile(
        "mma.sync.aligned.m16n8k16.row.col.f32.f16.f16.f32 "
        "{%0,%1,%2,%3}, {%4,%5,%6,%7}, {%8,%9}, {%0,%1,%2,%3};"
        : "+f"(d[0]), "+f"(d[1]), "+f"(d[2]), "+f"(d[3])
        : "r"(a[0]), "r"(a[1]), "r"(a[2]), "r"(a[3]), "r"(b0), "r"(b1));
}
__device__ __forceinline__ void ldsm4(unsigned& r0, unsigned& r1, unsigned& r2, unsigned& r3,
                                      unsigned a) {
    asm volatile("ldmatrix.sync.aligned.m8n8.x4.shared.b16 {%0,%1,%2,%3}, [%4];"
                 : "=r"(r0), "=r"(r1), "=r"(r2), "=r"(r3) : "r"(a));
}
__device__ __forceinline__ void ldsm2(unsigned& r0, unsigned& r1, unsigned a) {
    asm volatile("ldmatrix.sync.aligned.m8n8.x2.shared.b16 {%0,%1}, [%2];"
                 : "=r"(r0), "=r"(r1) : "r"(a));
}
__device__ __forceinline__ unsigned exp2h2(float lo, float hi) {
    unsigned r;
    asm("{\n\t.reg .b32 t;\n\tcvt.rn.f16x2.f32 t, %2, %1;\n\tex2.approx.f16x2 %0, t;\n\t}"
        : "=r"(r) : "f"(lo), "f"(hi));
    return r;
}
__device__ __forceinline__ float ex2f(float x) {
    float y;
    asm("ex2.approx.ftz.f32 %0, %1;" : "=f"(y) : "f"(x));
    return y;
}
__device__ __forceinline__ void cp16(unsigned dst, const void* src) {
    asm volatile("cp.async.cg.shared.global [%0], [%1], 16;" :: "r"(dst), "l"(src));
}
__device__ __forceinline__ void cp16p(unsigned dst, const void* src, int sz) {
    asm volatile("cp.async.cg.shared.global [%0], [%1], 16, %2;" :: "r"(dst), "l"(src), "r"(sz));
}
#define CP_COMMIT() asm volatile("cp.async.commit_group;")
#define CP_WAIT(n)  asm volatile("cp.async.wait_group %0;" :: "n"(n))

// ---------------- merged misc prep ----------------
__global__ void prep_misc_k(const float* __restrict__ Wx, const float* __restrict__ Wig,
                            const float* __restrict__ Wi, const float* __restrict__ Wf,
                            const float* __restrict__ Wg, const float* __restrict__ Wo) {
    int i = blockIdx.x * 256 + threadIdx.x;
    if (blockIdx.y == 0) {
        if (i >= 512 * 768) return;
        int co = i / 768, ci = i % 768;
        float v = (ci < 256) ? Wx[co * 256 + ci] : Wig[co * 512 + (ci - 256)];
        g_wproj16[i] = __float2half(v);
    } else if (blockIdx.y == 1) {
        const int nk = NB * GG * (KROWS - DD) * 64;
        if (i < nk) {
            int c = i & 63;
            int r = (i >> 6) % (KROWS - DD);
            int hd = i / ((KROWS - DD) * 64);
            g_kt16[((size_t)hd * KROWS + DD + r) * 64 + c] = __float2half(0.f);
        }
        const int nv = NB * GG * 64 * (VROWS - DD);
        if (i < nv) {
            int p = i % (VROWS - DD);
            int row = i / (VROWS - DD);
            g_vth[(size_t)row * VROWS + DD + p] = __float2half(0.f);
        }
        if (i < 256) g_vth[NB * GG * 64 * VROWS + i] = __float2half(0.f);
    } else {
        if (i >= 4 * GG * 64 * 64) return;
        int ci = i & 63;
        int co = (i >> 6) & 63;
        int g  = (i >> 12) & 7;
        int slot = i >> 15;
        const float* W = (slot == 0) ? Wi : (slot == 1) ? Wf : (slot == 2) ? Wg : Wo;
        g_wa16[((slot * GG + g) * 64 + co) * 64 + ci] = __float2half(W[(g * 64 + co) * 64 + ci]);
    }
}

__global__ void prep_wc_all_k(const float* __restrict__ Wq, const float* __restrict__ Wk,
                              const float* __restrict__ Wv, const float* __restrict__ Wi,
                              const float* __restrict__ Wf, const float* __restrict__ Wg,
                              const float* __restrict__ Wo, const float* __restrict__ tau) {
    int slot = blockIdx.y;
    const float* W;
    switch (slot) {
        case 0: W = Wq; break; case 1: W = Wk; break; case 2: W = Wv; break;
        case 3: W = Wi; break; case 4: W = Wf; break; case 5: W = Wg; break;
        default: W = Wo; break;
    }
    int i = blockIdx.x * 256 + threadIdx.x;
    if (i >= GG * 128 * 9 * 64) return;
    int co = i & 63;
    int tap = (i >> 6) % 9;
    int ci = (i / 576) & 127;
    int g  = i / (576 * 128);
    float v = W[((g * 64 + co) * 128 + ci) * 9 + tap];
    if (slot == 0) v *= tau[g] * 1.44269504f;
    g_wc16[slot][g][ci >> 4][tap][co][ci & 15] = __float2half(v);
}

// x_in + h -> g_in16 [px][768] f16
__global__ void __launch_bounds__(256) copy_in16_k(const float* __restrict__ x_in,
                                                   const float* __restrict__ h) {
    int n = blockIdx.z;
    int px = blockIdx.x * 256 + threadIdx.x;
    __half2* dst = (__half2*)&g_in16[n][px][0];
    const float* xb = x_in + (size_t)n * 256 * HW + px;
    const float* hb = h + (size_t)n * 512 * HW + px;
#pragma unroll 4
    for (int c2 = 0; c2 < 128; c2++)
        dst[c2] = __floats2half2_rn(xb[(2 * c2) * HW], xb[(2 * c2 + 1) * HW]);
#pragma unroll 4
    for (int c2 = 0; c2 < 256; c2++)
        dst[128 + c2] = __floats2half2_rn(hb[(2 * c2) * HW], hb[(2 * c2 + 1) * HW]);
}

// ---------------- proj 1x1 via f16 mma (256 px/block) + h transpose fold ----------------
#define PJ_IP 40
#define PJI (256 * PJ_IP)   // 10240 halves
#define PJW (64 * PJ_IP)    // 2560 halves
#define PJ_SMEM ((2 * PJI + 2 * PJW) * 2)   // 51,200 B

__global__ void __launch_bounds__(256) projmma_k(const float* __restrict__ h) {
    extern __shared__ __half spj[];
    int n = blockIdx.z, g = blockIdx.y, pxt = blockIdx.x;
    int pbase = pxt * 256;
    int t = threadIdx.x, w = t >> 5, lane = t & 31;
    int grp = lane >> 2, tg = lane & 3;

    unsigned suI = (unsigned)__cvta_generic_to_shared(spj);
    unsigned suW = suI + 2 * PJI * 2;

    float acc[2][8][4];
#pragma unroll
    for (int mg = 0; mg < 2; mg++)
#pragma unroll
        for (int nt = 0; nt < 8; nt++)
#pragma unroll
            for (int r = 0; r < 4; r++) acc[mg][nt][r] = 0.f;

    auto stage = [&](int it, int buf) {
        int cb = it * 32;
        for (int idx = t; idx < 1024; idx += 256) {
            int px = idx >> 2, seg = idx & 3;
            cp16(suI + (buf * PJI + px * PJ_IP + seg * 8) * 2,
                 &g_in16[n][pbase + px][cb + seg * 8]);
        }
        {
            int co = t >> 2, seg = t & 3;
            if (co < 64)
                cp16(suW + (buf * PJW + co * PJ_IP + seg * 8) * 2,
                     g_wproj16 + (g * 64 + co) * 768 + cb + seg * 8);
        }
    };

    stage(0, 0);
    CP_COMMIT();

    // fold: h -> xh upper half (thread t owns px = pbase + t, 64 channels)
    {
        __half2* dst = (__half2*)&g_xh16[n][g][pbase + t][64];
        const float* hb = h + ((size_t)n * 512 + g * 64) * HW + pbase + t;
#pragma unroll 8
        for (int c2 = 0; c2 < 32; c2++)
            dst[c2] = __floats2half2_rn(hb[(2 * c2) * HW], hb[(2 * c2 + 1) * HW]);
    }

    for (int it = 0; it < 24; it++) {
        int buf = it & 1;
        if (it + 1 < 24) { stage(it + 1, buf ^ 1); CP_COMMIT(); CP_WAIT(1); }
        else CP_WAIT(0);
        __syncthreads();
        unsigned bI = suI + buf * PJI * 2;
        unsigned bW = suW + buf * PJW * 2;
#pragma unroll
        for (int kc = 0; kc < 2; kc++) {
            unsigned b[8][2];
#pragma unroll
            for (int nt = 0; nt < 8; nt++)
                ldsm2(b[nt][0], b[nt][1],
                      bW + ((nt * 8 + (lane & 7)) * PJ_IP + kc * 16 + ((lane >> 3) & 1) * 8) * 2);
#pragma unroll
            for (int mg = 0; mg < 2; mg++) {
                unsigned a[4];
                ldsm4(a[0], a[1], a[2], a[3],
                      bI + ((w * 32 + mg * 16 + (lane & 15)) * PJ_IP
                            + kc * 16 + (lane >> 4) * 8) * 2);
#pragma unroll
                for (int nt = 0; nt < 8; nt++) mma_f16(acc[mg][nt], a, b[nt][0], b[nt][1]);
            }
        }
        __syncthreads();
    }

    __half* xb = &g_xh16[n][g][0][0];
#pragma unroll
    for (int mg = 0; mg < 2; mg++) {
        int px0 = pbase + w * 32 + mg * 16 + grp;
#pragma unroll
        for (int nt = 0; nt < 8; nt++) {
            int co = nt * 8 + 2 * tg;
            *(__half2*)&xb[(size_t)px0 * 128 + co] =
                __floats2half2_rn(acc[mg][nt][0], acc[mg][nt][1]);
            *(__half2*)&xb[(size_t)(px0 + 8) * 128 + co] =
                __floats2half2_rn(acc[mg][nt][2], acc[mg][nt][3]);
        }
    }
}

// ---------------- fused grouped 3x3 convs: 256 thr, m4/nt4, 32-ci weight chunks ----------------
#define CIN_PITCH 136
#define CIN_BUF (361 * CIN_PITCH)      // 49096 halves
#define CW_PITCH 24
#define CW_BUF (1152 * CW_PITCH)       // 27648 halves
#define CONV_SMEM ((CIN_BUF + 2 * CW_BUF) * 2)   // 208,784 B

__global__ void __launch_bounds__(256) conv3fused_k() {
    extern __shared__ __half smc[];
    unsigned su_in = (unsigned)__cvta_generic_to_shared(smc);
    unsigned su_w  = su_in + CIN_BUF * 2;

    int g = blockIdx.y, n = blockIdx.z;
    int ty0 = (blockIdx.x / 3) * 16, tx0 = (blockIdx.x % 3) * 16;
    int t = threadIdx.x, w = t >> 5, lane = t & 31;
    int pxg = w & 3, cog = w >> 2;   // 4 y-groups of 4 rows, 2 co-halves
    int grp = lane >> 2, tg = lane & 3;
    int hbase = n * GG + g;

    const __half* xb = &g_xh16[n][g][0][0];

    // stage full input halo tile once: 19x19 px x 128 ci
    for (int idx = t; idx < 361 * 16; idx += 256) {
        int row = idx >> 4, seg = idx & 15;
        int y = row / 19, x = row - y * 19;
        int iy = ty0 - 1 + y, ix = tx0 - 1 + x;
        bool ok = ((unsigned)iy < 48u) && ((unsigned)ix < 48u);
        const __half* src = xb + (size_t)(ok ? iy * 48 + ix : 0) * 128 + seg * 8;
        cp16p(su_in + (row * CIN_PITCH + seg * 8) * 2, src, ok ? 16 : 0);
    }
    CP_COMMIT();

    auto stageW = [&](int s, int buf) {
        int slot = s >> 2, q4 = s & 3;
        const __half* wb = &g_wc16[slot][g][0][0][0][0];
        for (int r = t; r < 1152; r += 256) {
            int it2 = r / 576, rem = r - it2 * 576;
            const __half* src = wb + (size_t)(q4 * 2 + it2) * 9216 + rem * 16;
            unsigned d = su_w + (buf * CW_BUF + r * CW_PITCH) * 2;
            cp16(d, src);
            cp16(d + 16, src + 8);
        }
    };

    stageW(0, 0);
    CP_COMMIT();

    float acc[4][4][4];
#pragma unroll
    for (int m = 0; m < 4; m++)
#pragma unroll
        for (int nt = 0; nt < 4; nt++)
#pragma unroll
            for (int r = 0; r < 4; r++) acc[m][nt][r] = 0.f;

    for (int s = 0; s < 28; s++) {
        int buf = s & 1;
        int slot = s >> 2, q4 = s & 3;
        if (s + 1 < 28) { stageW(s + 1, buf ^ 1); CP_COMMIT(); CP_WAIT(1); }
        else CP_WAIT(0);
        __syncthreads();

        int off = (slot == 1 || slot == 2) ? 1 : 0;   // k,v are pad=0
        unsigned bw = su_w + buf * CW_BUF * 2;

#pragma unroll
        for (int it2 = 0; it2 < 2; it2++) {
            int cioff = (q4 * 2 + it2) * 16;
#pragma unroll
            for (int kh = 0; kh < 3; kh++) {
#pragma unroll
                for (int kw = 0; kw < 3; kw++) {
                    unsigned b[4][2];
#pragma unroll
                    for (int nt = 0; nt < 4; nt++) {
                        unsigned addr = bw + ((it2 * 576 + (kh * 3 + kw) * 64 + cog * 32
                                               + nt * 8 + (lane & 7)) * CW_PITCH
                                              + ((lane >> 3) & 1) * 8) * 2;
                        ldsm2(b[nt][0], b[nt][1], addr);
                    }
#pragma unroll
                    for (int m = 0; m < 4; m++) {
                        int row = (pxg * 4 + m + kh + off) * 19 + (lane & 15) + kw + off;
                        unsigned a[4];
                        ldsm4(a[0], a[1], a[2], a[3],
                              su_in + (row * CIN_PITCH + cioff + (lane >> 4) * 8) * 2);
#pragma unroll
                        for (int nt = 0; nt < 4; nt++)
                            mma_f16(acc[m][nt], a, b[nt][0], b[nt][1]);
                    }
                }
            }
        }
        __syncthreads();

        if (q4 == 3) {   // slot complete: write out, reset acc
#pragma unroll
            for (int m = 0; m < 4; m++) {
                int y = ty0 + pxg * 4 + m;
#pragma unroll
                for (int nt = 0; nt < 4; nt++) {
                    int co = cog * 32 + nt * 8 + 2 * tg;
                    int x1 = tx0 + grp, x2 = x1 + 8;
                    if (slot == 1) {          // K f16 [d][c]
                        if (y < 46) {
                            if (x1 < 46)
                                *(__half2*)&g_kt16[((size_t)hbase * KROWS + y * 46 + x1) * 64 + co] =
                                    __floats2half2_rn(acc[m][nt][0], acc[m][nt][1]);
                            if (x2 < 46)
                                *(__half2*)&g_kt16[((size_t)hbase * KROWS + y * 46 + x2) * 64 + co] =
                                    __floats2half2_rn(acc[m][nt][2], acc[m][nt][3]);
                        }
                    } else if (slot == 2) {   // V f16 [c][d]
                        if (y < 46) {
                            if (x1 < 46) {
                                int d = y * 46 + x1;
                                g_vth[(size_t)(hbase * 64 + co) * VROWS + d] = __float2half(acc[m][nt][0]);
                                g_vth[(size_t)(hbase * 64 + co + 1) * VROWS + d] = __float2half(acc[m][nt][1]);
                            }
                            if (x2 < 46) {
                                int d = y * 46 + x2;
                                g_vth[(size_t)(hbase * 64 + co) * VROWS + d] = __float2half(acc[m][nt][2]);
                                g_vth[(size_t)(hbase * 64 + co + 1) * VROWS + d] = __float2half(acc[m][nt][3]);
                            }
                        }
                    } else {                  // Q / gates f16 [px][c]
                        __half* ob = (slot == 0) ? g_qt16 : &g_gx16[slot - 3][0];
                        *(__half2*)&ob[((size_t)hbase * HW + y * 48 + x1) * 64 + co] =
                            __floats2half2_rn(acc[m][nt][0], acc[m][nt][1]);
                        *(__half2*)&ob[((size_t)hbase * HW + y * 48 + x2) * 64 + co] =
                            __floats2half2_rn(acc[m][nt][2], acc[m][nt][3]);
                    }
                }
            }
#pragma unroll
            for (int m = 0; m < 4; m++)
#pragma unroll
                for (int nt = 0; nt < 4; nt++)
#pragma unroll
                    for (int r = 0; r < 4; r++) acc[m][nt][r] = 0.f;
        }
    }
}

// ---------------- flash attention: all-f16 mma (unchanged) ----------------
#define SQB 9216
#define SKB 9216
#define SVB 9792
#define ATTN_SMEM ((SQB + 2 * SKB + 2 * SVB) * 2)

__global__ void __launch_bounds__(256) attn_k() {
    extern __shared__ __half sma[];
    __half* sQ = sma;
    __half* sK = sma + SQB;
    __half* sV = sK + 2 * SKB;

    int n = blockIdx.z, g = blockIdx.y;
    int head = n * GG + g;
    int q0 = blockIdx.x * 128;
    int t = threadIdx.x, w = t >> 5, lane = t & 31;
    int grp = lane >> 2, tg = lane & 3;
    int qb = w * 16;

    unsigned suQ = (unsigned)__cvta_generic_to_shared(sQ);
    unsigned suK = (unsigned)__cvta_generic_to_shared(sK);
    unsigned suV = (unsigned)__cvta_generic_to_shared(sV);

    for (int idx = t; idx < 1024; idx += 256) {
        int q = idx >> 3, seg = idx & 7;
        cp16(suQ + (q * 72 + seg * 8) * 2,
             g_qt16 + ((size_t)head * HW + q0 + q) * 64 + seg * 8);
    }
    for (int idx = t; idx < 2 * 8 * 136; idx += 256) {
        int buf = idx / (8 * 136);
        int r = idx % (8 * 136);
        int row = 64 + r / 136, col = r % 136;
        sV[buf * SVB + row * 136 + col] = __float2half(row == 64 ? 1.f : 0.f);
    }

    auto stage = [&](int ch, int buf) {
        int db = ch * 128;
        const __half* ksrc = g_kt16 + ((size_t)head * KROWS + db) * 64;
        for (int idx = t; idx < 1024; idx += 256) {
            int d = idx >> 3, seg = idx & 7;
            cp16(suK + (buf * SKB + d * 72 + seg * 8) * 2, ksrc + d * 64 + seg * 8);
        }
        const __half* vsrc = g_vth + (size_t)head * 64 * VROWS + db;
        for (int idx = t; idx < 1024; idx += 256) {
            int c = idx >> 4, seg = idx & 15;
            cp16(suV + (buf * SVB + c * 136 + seg * 8) * 2, vsrc + (size_t)c * VROWS + seg * 8);
        }
    };

    stage(0, 0);
    CP_COMMIT();

    float O[9][4];
#pragma unroll
    for (int nt = 0; nt < 9; nt++)
#pragma unroll
        for (int r = 0; r < 4; r++) O[nt][r] = 0.f;
    float m0 = -1e30f, m1 = -1e30f;
    unsigned aQ[4][4];

    const int nch = KROWS / 128;
    for (int ch = 0; ch < nch; ch++) {
        int buf = ch & 1;
        if (ch + 1 < nch) { stage(ch + 1, buf ^ 1); CP_COMMIT(); CP_WAIT(1); }
        else CP_WAIT(0);
        __syncthreads();

        if (ch == 0) {
#pragma unroll
            for (int kc = 0; kc < 4; kc++)
                ldsm4(aQ[kc][0], aQ[kc][1], aQ[kc][2], aQ[kc][3],
                      suQ + ((qb + (lane & 15)) * 72 + kc * 16 + (lane >> 4) * 8) * 2);
        }

        unsigned bK = suK + buf * SKB * 2;
        const __half* sVb = sV + buf * SVB;

        float S[16][4];
#pragma unroll
        for (int np = 0; np < 8; np++) {
            S[2 * np][0] = S[2 * np][1] = S[2 * np][2] = S[2 * np][3] = 0.f;
            S[2 * np + 1][0] = S[2 * np + 1][1] = S[2 * np + 1][2] = S[2 * np + 1][3] = 0.f;
#pragma unroll
            for (int kc = 0; kc < 4; kc++) {
                unsigned b0, b1, b2, b3;
                ldsm4(b0, b1, b2, b3,
                      bK + ((np * 16 + (lane & 7) + (lane >> 4) * 8) * 72
                            + kc * 16 + ((lane >> 3) & 1) * 8) * 2);
                mma_f16(S[2 * np], aQ[kc], b0, b1);
                mma_f16(S[2 * np + 1], aQ[kc], b2, b3);
            }
        }

        if (ch == nch - 1) {
            int cb = ch * 128 + 2 * tg;
#pragma unroll
            for (int nt = 0; nt < 16; nt++) {
                int c = cb + nt * 8;
                if (c >= DD)     { S[nt][0] = -1e30f; S[nt][2] = -1e30f; }
                if (c + 1 >= DD) { S[nt][1] = -1e30f; S[nt][3] = -1e30f; }
            }
        }

        float rm0 = -1e30f, rm1 = -1e30f;
#pragma unroll
        for (int nt = 0; nt < 16; nt++) {
            rm0 = fmaxf(rm0, fmaxf(S[nt][0], S[nt][1]));
            rm1 = fmaxf(rm1, fmaxf(S[nt][2], S[nt][3]));
        }
        rm0 = fmaxf(rm0, __shfl_xor_sync(0xffffffffu, rm0, 1));
        rm0 = fmaxf(rm0, __shfl_xor_sync(0xffffffffu, rm0, 2));
        rm1 = fmaxf(rm1, __shfl_xor_sync(0xffffffffu, rm1, 1));
        rm1 = fmaxf(rm1, __shfl_xor_sync(0xffffffffu, rm1, 2));
        float mn0 = fmaxf(m0, rm0), mn1 = fmaxf(m1, rm1);
        float a0 = ex2f(m0 - mn0), a1 = ex2f(m1 - mn1);
        m0 = mn0; m1 = mn1;
#pragma unroll
        for (int nt = 0; nt < 9; nt++) {
            O[nt][0] *= a0; O[nt][1] *= a0;
            O[nt][2] *= a1; O[nt][3] *= a1;
        }

        unsigned pf[16][2];
#pragma unroll
        for (int nt = 0; nt < 16; nt++) {
            pf[nt][0] = exp2h2(S[nt][0] - m0, S[nt][1] - m0);
            pf[nt][1] = exp2h2(S[nt][2] - m1, S[nt][3] - m1);
        }

#pragma unroll
        for (int kc = 0; kc < 8; kc++) {
            unsigned A4[4] = {pf[2 * kc][0], pf[2 * kc][1], pf[2 * kc + 1][0], pf[2 * kc + 1][1]};
#pragma unroll
            for (int nt = 0; nt < 9; nt++) {
                const __half* vp = &sVb[(nt * 8 + grp) * 136 + kc * 16 + 2 * tg];
                unsigned b0 = *(const unsigned*)vp;
                unsigned b1 = *(const unsigned*)(vp + 8);
                mma_f16(O[nt], A4, b0, b1);
            }
        }
        __syncthreads();
    }

    float l0 = __shfl_sync(0xffffffffu, O[8][0], lane & ~3);
    float l1 = __shfl_sync(0xffffffffu, O[8][2], lane & ~3);
    float inv0 = 1.f / l0, inv1 = 1.f / l1;
#pragma unroll
    for (int nt = 0; nt < 8; nt++) {
        int c = nt * 8 + 2 * tg;
        *(__half2*)&g_at16[((size_t)head * HW + q0 + qb + grp) * 64 + c] =
            __floats2half2_rn(O[nt][0] * inv0, O[nt][1] * inv0);
        *(__half2*)&g_at16[((size_t)head * HW + q0 + qb + grp + 8) * 64 + c] =
            __floats2half2_rn(O[nt][2] * inv1, O[nt][3] * inv1);
    }
}

// ---------------- final: gate 1x1 via f16 mma + gx f16 smem staging + LSTM ----------------
#define FA_HALVES (64 * 72)
#define FW_HALVES (256 * 72)
#define FG_OFF (FA_HALVES + FW_HALVES)         // halves; s_gate f32 starts at byte 2*FG_OFF
#define FGX_OFF (FG_OFF + 64 * 257 * 2)        // halves offset of s_gx (after f32 s_gate)
#define FGX_PITCH 66
#define FINAL_SMEM ((FGX_OFF + 4 * 64 * FGX_PITCH) * 2)

__device__ __forceinline__ float tanh_fast(float x) {
    float e = __expf(-2.f * fabsf(x));
    float r = (1.f - e) / (1.f + e);
    return copysignf(r, x);
}

__global__ void __launch_bounds__(256) final_k(const float* __restrict__ c_in,
                                               const float* __restrict__ b_i,
                                               const float* __restrict__ b_f,
                                               const float* __restrict__ b_g,
                                               const float* __restrict__ b_o,
                                               float* __restrict__ out) {
    extern __shared__ __half smf[];
    unsigned suA = (unsigned)__cvta_generic_to_shared(smf);
    unsigned suW = suA + FA_HALVES * 2;
    float* s_gate = (float*)(smf + FG_OFF);
    __half* s_gx = smf + FGX_OFF;

    int n = blockIdx.z, g = blockIdx.y, pxt = blockIdx.x;
    int pxbase = pxt * 64;
    int head = n * GG + g;
    int t = threadIdx.x, w = t >> 5, lane = t & 31;
    int grp = lane >> 2, tg = lane & 3;
    int pxg = w >> 1, nh = w & 1;

    for (int r = t; r < 512; r += 256) {
        int px = r >> 3, seg = r & 7;
        cp16(suA + (px * 72 + seg * 8) * 2,
             g_at16 + ((size_t)head * HW + pxbase + px) * 64 + seg * 8);
    }
    for (int r = t; r < 2048; r += 256) {
        int row = r >> 3, seg = r & 7;
        cp16(suW + (row * 72 + seg * 8) * 2,
             g_wa16 + ((size_t)((row >> 6) * GG + g) * 64 + (row & 63)) * 64 + seg * 8);
    }
    CP_COMMIT();

    // stage gx (4 gates x 64 px x 64 c) via vector ld + sts (pitch 66: conflict-free reads)
    for (int r = t; r < 2048; r += 256) {
        int gate = r >> 9, rem = r & 511;
        int px = rem >> 3, seg = rem & 7;
        float4 v = *(const float4*)&g_gx16[gate][((size_t)head * HW + pxbase + px) * 64 + seg * 8];
        __half* d = s_gx + gate * 64 * FGX_PITCH + px * FGX_PITCH + seg * 8;
        *(unsigned*)(d + 0) = ((const unsigned*)&v)[0];
        *(unsigned*)(d + 2) = ((const unsigned*)&v)[1];
        *(unsigned*)(d + 4) = ((const unsigned*)&v)[2];
        *(unsigned*)(d + 6) = ((const unsigned*)&v)[3];
    }
    CP_WAIT(0);
    __syncthreads();

    unsigned aA[4][4];
#pragma unroll
    for (int kc = 0; kc < 4; kc++)
        ldsm4(aA[kc][0], aA[kc][1], aA[kc][2], aA[kc][3],
              suA + ((pxg * 16 + (lane & 15)) * 72 + kc * 16 + (lane >> 4) * 8) * 2);

    float acc[16][4];
#pragma unroll
    for (int nt = 0; nt < 16; nt++) {
        acc[nt][0] = acc[nt][1] = acc[nt][2] = acc[nt][3] = 0.f;
#pragma unroll
        for (int kc = 0; kc < 4; kc++) {
            unsigned b0, b1;
            ldsm2(b0, b1, suW + ((nh * 128 + nt * 8 + (lane & 7)) * 72
                                 + kc * 16 + ((lane >> 3) & 1) * 8) * 2);
            mma_f16(acc[nt], aA[kc], b0, b1);
        }
    }

#pragma unroll
    for (int nt = 0; nt < 16; nt++) {
        int col = nh * 128 + nt * 8 + 2 * tg;
        int r0 = pxg * 16 + grp;
        s_gate[r0 * 257 + col]           = acc[nt][0];
        s_gate[r0 * 257 + col + 1]       = acc[nt][1];
        s_gate[(r0 + 8) * 257 + col]     = acc[nt][2];
        s_gate[(r0 + 8) * 257 + col + 1] = acc[nt][3];
    }
    __syncthreads();

    int pxl = t & 63, cb0 = t >> 6;
    int pxglob = pxbase + pxl;
#pragma unroll 4
    for (int k = 0; k < 16; k++) {
        int co = k * 4 + cb0;
        int ch = g * 64 + co;
        size_t gi = ((size_t)(n * 512 + ch)) * HW + pxglob;
        float ai = s_gate[pxl * 257 + co]       + b_i[ch]
                 + __half2float(s_gx[0 * 64 * FGX_PITCH + pxl * FGX_PITCH + co]);
        float af = s_gate[pxl * 257 + 64 + co]  + b_f[ch]
                 + __half2float(s_gx[1 * 64 * FGX_PITCH + pxl * FGX_PITCH + co]);
        float ag = s_gate[pxl * 257 + 128 + co] + b_g[ch]
                 + __half2float(s_gx[2 * 64 * FGX_PITCH + pxl * FGX_PITCH + co]);
        float ao = s_gate[pxl * 257 + 192 + co] + b_o[ch]
                 + __half2float(s_gx[3 * 64 * FGX_PITCH + pxl * FGX_PITCH + co]);
        float iv = 1.f / (1.f + __expf(-ai));
        float fv = 1.f / (1.f + __expf(-af));
        float gv = tanh_fast(ag);
        float ov = 1.f / (1.f + __expf(-ao));
        float cn = fv * c_in[gi] + iv * gv;
        out[gi] = ov * tanh_fast(cn);
    }
}

// ---------------- launch ----------------
extern "C" void kernel_launch(void* const* d_in, const int* in_sizes, int n_in,
                              void* d_out, int out_size) {
    const float* x_in = (const float*)d_in[0];
    const float* h    = (const float*)d_in[1];
    const float* c    = (const float*)d_in[2];
    const float* tau  = (const float*)d_in[3];
    const float* W_x  = (const float*)d_in[4];
    const float* W_ig = (const float*)d_in[5];
    const float* W_q  = (const float*)d_in[6];
    const float* W_k  = (const float*)d_in[7];
    const float* W_v  = (const float*)d_in[8];
    const float* Wi_a = (const float*)d_in[9];
    const float* Wi_x = (const float*)d_in[10];
    const float* b_i  = (const float*)d_in[11];
    const float* Wf_a = (const float*)d_in[12];
    const float* Wf_x = (const float*)d_in[13];
    const float* b_f  = (const float*)d_in[14];
    const float* Wg_a = (const float*)d_in[15];
    const float* Wg_x = (const float*)d_in[16];
    const float* b_g  = (const float*)d_in[17];
    const float* Wo_a = (const float*)d_in[18];
    const float* Wo_x = (const float*)d_in[19];
    const float* b_o  = (const float*)d_in[20];
    float* out = (float*)d_out;

    cudaFuncSetAttribute(attn_k, cudaFuncAttributeMaxDynamicSharedMemorySize, ATTN_SMEM);
    cudaFuncSetAttribute(conv3fused_k, cudaFuncAttributeMaxDynamicSharedMemorySize, CONV_SMEM);
    cudaFuncSetAttribute(projmma_k, cudaFuncAttributeMaxDynamicSharedMemorySize, PJ_SMEM);
    cudaFuncSetAttribute(final_k, cudaFuncAttributeMaxDynamicSharedMemorySize, FINAL_SMEM);

    prep_misc_k<<<dim3(1536, 3), 256>>>(W_x, W_ig, Wi_a, Wf_a, Wg_a, Wo_a);
    prep_wc_all_k<<<dim3((8 * 128 * 9 * 64 + 255) / 256, 7), 256>>>(W_q, W_k, W_v,
                                                                    Wi_x, Wf_x, Wg_x, Wo_x, tau);
    copy_in16_k<<<dim3(9, 1, NB), 256>>>(x_in, h);
    projmma_k<<<dim3(9, GG, NB), 256, PJ_SMEM>>>(h);

    conv3fused_k<<<dim3(9, GG, NB), 256, CONV_SMEM>>>();   // all 7 convs, one wave

    attn_k<<<dim3(HW / 128, GG, NB), 256, ATTN_SMEM>>>();

    final_k<<<dim3(HW / 64, GG, NB), 256, FINAL_SMEM>>>(c, b_i, b_f, b_g, b_o, out);
}

// round 13
// speedup vs baseline: 1.0814x; 1.0814x over previous
#include <cuda_runtime.h>
#include <cuda_fp16.h>

// Problem constants
#define NB   2
#define GG   8
#define HW   2304     // 48*48
#define DD   2116     // 46*46
#define KROWS 2176    // DD padded to chunk multiple (17*128)
#define VROWS 2120    // DD padded for f16 16B alignment

// ---------------- scratch ----------------
__device__ __align__(256) __half g_xh16[NB][GG][HW][128];     // xh f16 [px][c]
__device__ __align__(256) __half g_in16[NB][HW][768];         // x_in+h f16 [px][c]
__device__ __align__(256) __half g_qt16[NB * GG * HW * 64];   // q [head][px][c] (tau*log2e folded)
__device__ __align__(256) __half g_kt16[NB * GG * KROWS * 64];// k [head][d][c]
__device__ __align__(256) __half g_vth[NB * GG * 64 * VROWS + 256]; // v [head][c][d]
__device__ __align__(256) __half g_at16[NB * GG * HW * 64];   // a [head][px][c]
__device__ float g_gx[4][NB * 512 * HW];                      // gate conv outputs f32 [c][px]
__device__ __align__(256) __half g_wproj16[512 * 768];        // [co][ci]
__device__ __align__(256) __half g_wc16[7][GG][8][9][64][16]; // conv weights f16
__device__ __align__(256) __half g_wa16[4 * GG * 64 * 64];    // [gate][g][co][ci]

// ---------------- asm helpers ----------------
__device__ __forceinline__ void mma_f16(float* d, const unsigned* a, unsigned b0, unsigned b1) {
    asm volatile(
        "mma.sync.aligned.m16n8k16.row.col.f32.f16.f16.f32 "
        "{%0,%1,%2,%3}, {%4,%5,%6,%7}, {%8,%9}, {%0,%1,%2,%3};"
        : "+f"(d[0]), "+f"(d[1]), "+f"(d[2]), "+f"(d[3])
        : "r"(a[0]), "r"(a[1]), "r"(a[2]), "r"(a[3]), "r"(b0), "r"(b1));
}
__device__ __forceinline__ void ldsm4(unsigned& r0, unsigned& r1, unsigned& r2, unsigned& r3,
                                      unsigned a) {
    asm volatile("ldmatrix.sync.aligned.m8n8.x4.shared.b16 {%0,%1,%2,%3}, [%4];"
                 : "=r"(r0), "=r"(r1), "=r"(r2), "=r"(r3) : "r"(a));
}
__device__ __forceinline__ void ldsm2(unsigned& r0, unsigned& r1, unsigned a) {
    asm volatile("ldmatrix.sync.aligned.m8n8.x2.shared.b16 {%0,%1}, [%2];"
                 : "=r"(r0), "=r"(r1) : "r"(a));
}
__device__ __forceinline__ unsigned exp2h2(float lo, float hi) {
    unsigned r;
    asm("{\n\t.reg .b32 t;\n\tcvt.rn.f16x2.f32 t, %2, %1;\n\tex2.approx.f16x2 %0, t;\n\t}"
        : "=r"(r) : "f"(lo), "f"(hi));
    return r;
}
__device__ __forceinline__ float ex2f(float x) {
    float y;
    asm("ex2.approx.ftz.f32 %0, %1;" : "=f"(y) : "f"(x));
    return y;
}
__device__ __forceinline__ void cp16(unsigned dst, const void* src) {
    asm volatile("cp.async.cg.shared.global [%0], [%1], 16;" :: "r"(dst), "l"(src));
}
__device__ __forceinline__ void cp16p(unsigned dst, const void* src, int sz) {
    asm volatile("cp.async.cg.shared.global [%0], [%1], 16, %2;" :: "r"(dst), "l"(src), "r"(sz));
}
#define CP_COMMIT() asm volatile("cp.async.commit_group;")
#define CP_WAIT(n)  asm volatile("cp.async.wait_group %0;" :: "n"(n))

// ---------------- merged misc prep ----------------
__global__ void prep_misc_k(const float* __restrict__ Wx, const float* __restrict__ Wig,
                            const float* __restrict__ Wi, const float* __restrict__ Wf,
                            const float* __restrict__ Wg, const float* __restrict__ Wo) {
    int i = blockIdx.x * 256 + threadIdx.x;
    if (blockIdx.y == 0) {
        if (i >= 512 * 768) return;
        int co = i / 768, ci = i % 768;
        float v = (ci < 256) ? Wx[co * 256 + ci] : Wig[co * 512 + (ci - 256)];
        g_wproj16[i] = __float2half(v);
    } else if (blockIdx.y == 1) {
        const int nk = NB * GG * (KROWS - DD) * 64;
        if (i < nk) {
            int c = i & 63;
            int r = (i >> 6) % (KROWS - DD);
            int hd = i / ((KROWS - DD) * 64);
            g_kt16[((size_t)hd * KROWS + DD + r) * 64 + c] = __float2half(0.f);
        }
        const int nv = NB * GG * 64 * (VROWS - DD);
        if (i < nv) {
            int p = i % (VROWS - DD);
            int row = i / (VROWS - DD);
            g_vth[(size_t)row * VROWS + DD + p] = __float2half(0.f);
        }
        if (i < 256) g_vth[NB * GG * 64 * VROWS + i] = __float2half(0.f);
    } else {
        if (i >= 4 * GG * 64 * 64) return;
        int ci = i & 63;
        int co = (i >> 6) & 63;
        int g  = (i >> 12) & 7;
        int slot = i >> 15;
        const float* W = (slot == 0) ? Wi : (slot == 1) ? Wf : (slot == 2) ? Wg : Wo;
        g_wa16[((slot * GG + g) * 64 + co) * 64 + ci] = __float2half(W[(g * 64 + co) * 64 + ci]);
    }
}

__global__ void prep_wc_all_k(const float* __restrict__ Wq, const float* __restrict__ Wk,
                              const float* __restrict__ Wv, const float* __restrict__ Wi,
                              const float* __restrict__ Wf, const float* __restrict__ Wg,
                              const float* __restrict__ Wo, const float* __restrict__ tau) {
    int slot = blockIdx.y;
    const float* W;
    switch (slot) {
        case 0: W = Wq; break; case 1: W = Wk; break; case 2: W = Wv; break;
        case 3: W = Wi; break; case 4: W = Wf; break; case 5: W = Wg; break;
        default: W = Wo; break;
    }
    int i = blockIdx.x * 256 + threadIdx.x;
    if (i >= GG * 128 * 9 * 64) return;
    int co = i & 63;
    int tap = (i >> 6) % 9;
    int ci = (i / 576) & 127;
    int g  = i / (576 * 128);
    float v = W[((g * 64 + co) * 128 + ci) * 9 + tap];
    if (slot == 0) v *= tau[g] * 1.44269504f;
    g_wc16[slot][g][ci >> 4][tap][co][ci & 15] = __float2half(v);
}

// merged transposing copies: y<8 -> h slice to xh upper half; y==8 -> x_in+h to g_in16
__global__ void __launch_bounds__(256) copy_merged_k(const float* __restrict__ x_in,
                                                     const float* __restrict__ h) {
    int n = blockIdx.z;
    int px = blockIdx.x * 256 + threadIdx.x;
    if (blockIdx.y < 8) {
        int g = blockIdx.y;
        __half2* dst = (__half2*)&g_xh16[n][g][px][64];
        const float* hb = h + (n * 512 + g * 64) * HW + px;
#pragma unroll 8
        for (int c2 = 0; c2 < 32; c2++)
            dst[c2] = __floats2half2_rn(hb[(2 * c2) * HW], hb[(2 * c2 + 1) * HW]);
    } else {
        __half2* dst = (__half2*)&g_in16[n][px][0];
        const float* xb = x_in + (size_t)n * 256 * HW + px;
        const float* hb = h + (size_t)n * 512 * HW + px;
#pragma unroll 4
        for (int c2 = 0; c2 < 128; c2++)
            dst[c2] = __floats2half2_rn(xb[(2 * c2) * HW], xb[(2 * c2 + 1) * HW]);
#pragma unroll 4
        for (int c2 = 0; c2 < 256; c2++)
            dst[128 + c2] = __floats2half2_rn(hb[(2 * c2) * HW], hb[(2 * c2 + 1) * HW]);
    }
}

// ---------------- proj 1x1 via f16 mma (R10 version: 128 px/block, 32-ci chunks) ----------------
#define PJ_IP 40
#define PJI (128 * PJ_IP)   // 5120 halves
#define PJW (64 * PJ_IP)    // 2560 halves

__global__ void __launch_bounds__(256) projmma_k() {
    __shared__ __align__(16) __half spj[2 * PJI + 2 * PJW];
    int n = blockIdx.z, g = blockIdx.y, pxt = blockIdx.x;
    int pbase = pxt * 128;
    int t = threadIdx.x, w = t >> 5, lane = t & 31;
    int grp = lane >> 2, tg = lane & 3;

    unsigned suI = (unsigned)__cvta_generic_to_shared(spj);
    unsigned suW = suI + 2 * PJI * 2;

    float acc[8][4];
#pragma unroll
    for (int nt = 0; nt < 8; nt++)
#pragma unroll
        for (int r = 0; r < 4; r++) acc[nt][r] = 0.f;

    auto stage = [&](int it, int buf) {
        int cb = it * 32;
        for (int idx = t; idx < 512; idx += 256) {
            int px = idx >> 2, seg = idx & 3;
            cp16(suI + (buf * PJI + px * PJ_IP + seg * 8) * 2,
                 &g_in16[n][pbase + px][cb + seg * 8]);
        }
        {
            int co = t >> 2, seg = t & 3;
            if (co < 64)
                cp16(suW + (buf * PJW + co * PJ_IP + seg * 8) * 2,
                     g_wproj16 + (g * 64 + co) * 768 + cb + seg * 8);
        }
    };

    stage(0, 0);
    CP_COMMIT();
    for (int it = 0; it < 24; it++) {
        int buf = it & 1;
        if (it + 1 < 24) { stage(it + 1, buf ^ 1); CP_COMMIT(); CP_WAIT(1); }
        else CP_WAIT(0);
        __syncthreads();
        unsigned bI = suI + buf * PJI * 2;
        unsigned bW = suW + buf * PJW * 2;
#pragma unroll
        for (int kc = 0; kc < 2; kc++) {
            unsigned a[4];
            ldsm4(a[0], a[1], a[2], a[3],
                  bI + ((w * 16 + (lane & 15)) * PJ_IP + kc * 16 + (lane >> 4) * 8) * 2);
#pragma unroll
            for (int nt = 0; nt < 8; nt++) {
                unsigned b0, b1;
                ldsm2(b0, b1, bW + ((nt * 8 + (lane & 7)) * PJ_IP + kc * 16
                                    + ((lane >> 3) & 1) * 8) * 2);
                mma_f16(acc[nt], a, b0, b1);
            }
        }
        __syncthreads();
    }

    __half* xb = &g_xh16[n][g][0][0];
    int px0 = pbase + w * 16 + grp;
#pragma unroll
    for (int nt = 0; nt < 8; nt++) {
        int co = nt * 8 + 2 * tg;
        *(__half2*)&xb[(size_t)px0 * 128 + co]       = __floats2half2_rn(acc[nt][0], acc[nt][1]);
        *(__half2*)&xb[(size_t)(px0 + 8) * 128 + co] = __floats2half2_rn(acc[nt][2], acc[nt][3]);
    }
}

// ---------------- fused grouped 3x3 convs: slot-paired A-fragment sharing ----------------
// 256 threads, m4/nt4. Passes: {k,v}(pad0), {q,i}, {f,g}, {o} — A ldsm4 shared across the pair.
#define CIN_PITCH 136
#define CIN_BUF (361 * CIN_PITCH)      // 49096 halves
#define CW_PITCH 24
#define CW_BUF (1152 * CW_PITCH)       // 27648 halves (2 slots x 576 rows)
#define CONV_SMEM ((CIN_BUF + 2 * CW_BUF) * 2)   // 208,784 B

__global__ void __launch_bounds__(256) conv3fused_k() {
    extern __shared__ __half smc[];
    unsigned su_in = (unsigned)__cvta_generic_to_shared(smc);
    unsigned su_w  = su_in + CIN_BUF * 2;

    int g = blockIdx.y, n = blockIdx.z;
    int ty0 = (blockIdx.x / 3) * 16, tx0 = (blockIdx.x % 3) * 16;
    int t = threadIdx.x, w = t >> 5, lane = t & 31;
    int pxg = w & 3, cog = w >> 2;
    int grp = lane >> 2, tg = lane & 3;
    int hbase = n * GG + g;

    const __half* xb = &g_xh16[n][g][0][0];

    // stage full input halo tile once: 19x19 px x 128 ci
    for (int idx = t; idx < 361 * 16; idx += 256) {
        int row = idx >> 4, seg = idx & 15;
        int y = row / 19, x = row - y * 19;
        int iy = ty0 - 1 + y, ix = tx0 - 1 + x;
        bool ok = ((unsigned)iy < 48u) && ((unsigned)ix < 48u);
        const __half* src = xb + (size_t)(ok ? iy * 48 + ix : 0) * 128 + seg * 8;
        cp16p(su_in + (row * CIN_PITCH + seg * 8) * 2, src, ok ? 16 : 0);
    }
    CP_COMMIT();

    // weight staging: stage sidx = p*8 + c16; both slots of pass p, 16-ci chunk c16
    auto stageW = [&](int sidx, int buf) {
        int p = sidx >> 3, c16 = sidx & 7;
        int s0 = (p == 0) ? 1 : (p == 1) ? 0 : (p == 2) ? 4 : 6;
        int s1 = (p == 0) ? 2 : (p == 1) ? 3 : (p == 2) ? 5 : 6;
        for (int r = t; r < 1152; r += 256) {
            int sl2 = r / 576, rem = r - sl2 * 576;
            int slot = sl2 ? s1 : s0;
            const __half* src = &g_wc16[slot][g][c16][0][0][0] + rem * 16;
            unsigned d = su_w + (buf * CW_BUF + r * CW_PITCH) * 2;
            cp16(d, src);
            cp16(d + 16, src + 8);
        }
    };

    stageW(0, 0);
    CP_COMMIT();

    float acc[2][4][4][4];
#pragma unroll
    for (int sl = 0; sl < 2; sl++)
#pragma unroll
        for (int m = 0; m < 4; m++)
#pragma unroll
            for (int nt = 0; nt < 4; nt++)
#pragma unroll
                for (int r = 0; r < 4; r++) acc[sl][m][nt][r] = 0.f;

    for (int p = 0; p < 4; p++) {
        int off = (p == 0) ? 1 : 0;   // pass 0 = {k,v} pad=0 -> +1 halo offset
        int nsl = (p == 3) ? 1 : 2;
        for (int c16 = 0; c16 < 8; c16++) {
            int sidx = p * 8 + c16;
            int buf = sidx & 1;
            if (sidx + 1 < 32) { stageW(sidx + 1, buf ^ 1); CP_COMMIT(); CP_WAIT(1); }
            else CP_WAIT(0);
            __syncthreads();

            unsigned bw = su_w + buf * CW_BUF * 2;
            int cioff = c16 * 16;
#pragma unroll
            for (int kh = 0; kh < 3; kh++) {
#pragma unroll
                for (int kw = 0; kw < 3; kw++) {
                    unsigned b[2][4][2];
#pragma unroll
                    for (int sl = 0; sl < 2; sl++) {
                        if (sl >= nsl) break;
#pragma unroll
                        for (int nt = 0; nt < 4; nt++) {
                            unsigned addr = bw + ((sl * 576 + (kh * 3 + kw) * 64 + cog * 32
                                                   + nt * 8 + (lane & 7)) * CW_PITCH
                                                  + ((lane >> 3) & 1) * 8) * 2;
                            ldsm2(b[sl][nt][0], b[sl][nt][1], addr);
                        }
                    }
#pragma unroll
                    for (int m = 0; m < 4; m++) {
                        int row = (pxg * 4 + m + kh + off) * 19 + (lane & 15) + kw + off;
                        unsigned a[4];
                        ldsm4(a[0], a[1], a[2], a[3],
                              su_in + (row * CIN_PITCH + cioff + (lane >> 4) * 8) * 2);
#pragma unroll
                        for (int sl = 0; sl < 2; sl++) {
                            if (sl >= nsl) break;
#pragma unroll
                            for (int nt = 0; nt < 4; nt++)
                                mma_f16(acc[sl][m][nt], a, b[sl][nt][0], b[sl][nt][1]);
                        }
                    }
                }
            }
            __syncthreads();
        }

        // pass complete: write both slots, reset acc
        int s0 = (p == 0) ? 1 : (p == 1) ? 0 : (p == 2) ? 4 : 6;
        int s1 = (p == 0) ? 2 : (p == 1) ? 3 : (p == 2) ? 5 : 6;
        for (int sl = 0; sl < nsl; sl++) {
            int slot = sl ? s1 : s0;
#pragma unroll
            for (int m = 0; m < 4; m++) {
                int y = ty0 + pxg * 4 + m;
#pragma unroll
                for (int nt = 0; nt < 4; nt++) {
                    float* ac = acc[sl][m][nt];
                    int co = cog * 32 + nt * 8 + 2 * tg;
                    int x1 = tx0 + grp, x2 = x1 + 8;
                    if (slot == 1) {          // K f16 [d][c]
                        if (y < 46) {
                            if (x1 < 46)
                                *(__half2*)&g_kt16[((size_t)hbase * KROWS + y * 46 + x1) * 64 + co] =
                                    __floats2half2_rn(ac[0], ac[1]);
                            if (x2 < 46)
                                *(__half2*)&g_kt16[((size_t)hbase * KROWS + y * 46 + x2) * 64 + co] =
                                    __floats2half2_rn(ac[2], ac[3]);
                        }
                    } else if (slot == 2) {   // V f16 [c][d]
                        if (y < 46) {
                            if (x1 < 46) {
                                int d = y * 46 + x1;
                                g_vth[(size_t)(hbase * 64 + co) * VROWS + d] = __float2half(ac[0]);
                                g_vth[(size_t)(hbase * 64 + co + 1) * VROWS + d] = __float2half(ac[1]);
                            }
                            if (x2 < 46) {
                                int d = y * 46 + x2;
                                g_vth[(size_t)(hbase * 64 + co) * VROWS + d] = __float2half(ac[2]);
                                g_vth[(size_t)(hbase * 64 + co + 1) * VROWS + d] = __float2half(ac[3]);
                            }
                        }
                    } else if (slot == 0) {   // Q f16 [px][c]
                        *(__half2*)&g_qt16[((size_t)hbase * HW + y * 48 + x1) * 64 + co] =
                            __floats2half2_rn(ac[0], ac[1]);
                        *(__half2*)&g_qt16[((size_t)hbase * HW + y * 48 + x2) * 64 + co] =
                            __floats2half2_rn(ac[2], ac[3]);
                    } else {                  // gates f32 [c][px]
                        float* ob = &g_gx[slot - 3][0] + (size_t)hbase * 64 * HW + y * 48;
                        ob[co * HW + x1] = ac[0];
                        ob[(co + 1) * HW + x1] = ac[1];
                        ob[co * HW + x2] = ac[2];
                        ob[(co + 1) * HW + x2] = ac[3];
                    }
                }
            }
        }
#pragma unroll
        for (int sl = 0; sl < 2; sl++)
#pragma unroll
            for (int m = 0; m < 4; m++)
#pragma unroll
                for (int nt = 0; nt < 4; nt++)
#pragma unroll
                    for (int r = 0; r < 4; r++) acc[sl][m][nt][r] = 0.f;
    }
}

// ---------------- flash attention: all-f16 mma (unchanged) ----------------
#define SQB 9216
#define SKB 9216
#define SVB 9792
#define ATTN_SMEM ((SQB + 2 * SKB + 2 * SVB) * 2)

__global__ void __launch_bounds__(256) attn_k() {
    extern __shared__ __half sma[];
    __half* sQ = sma;
    __half* sK = sma + SQB;
    __half* sV = sK + 2 * SKB;

    int n = blockIdx.z, g = blockIdx.y;
    int head = n * GG + g;
    int q0 = blockIdx.x * 128;
    int t = threadIdx.x, w = t >> 5, lane = t & 31;
    int grp = lane >> 2, tg = lane & 3;
    int qb = w * 16;

    unsigned suQ = (unsigned)__cvta_generic_to_shared(sQ);
    unsigned suK = (unsigned)__cvta_generic_to_shared(sK);
    unsigned suV = (unsigned)__cvta_generic_to_shared(sV);

    for (int idx = t; idx < 1024; idx += 256) {
        int q = idx >> 3, seg = idx & 7;
        cp16(suQ + (q * 72 + seg * 8) * 2,
             g_qt16 + ((size_t)head * HW + q0 + q) * 64 + seg * 8);
    }
    for (int idx = t; idx < 2 * 8 * 136; idx += 256) {
        int buf = idx / (8 * 136);
        int r = idx % (8 * 136);
        int row = 64 + r / 136, col = r % 136;
        sV[buf * SVB + row * 136 + col] = __float2half(row == 64 ? 1.f : 0.f);
    }

    auto stage = [&](int ch, int buf) {
        int db = ch * 128;
        const __half* ksrc = g_kt16 + ((size_t)head * KROWS + db) * 64;
        for (int idx = t; idx < 1024; idx += 256) {
            int d = idx >> 3, seg = idx & 7;
            cp16(suK + (buf * SKB + d * 72 + seg * 8) * 2, ksrc + d * 64 + seg * 8);
        }
        const __half* vsrc = g_vth + (size_t)head * 64 * VROWS + db;
        for (int idx = t; idx < 1024; idx += 256) {
            int c = idx >> 4, seg = idx & 15;
            cp16(suV + (buf * SVB + c * 136 + seg * 8) * 2, vsrc + (size_t)c * VROWS + seg * 8);
        }
    };

    stage(0, 0);
    CP_COMMIT();

    float O[9][4];
#pragma unroll
    for (int nt = 0; nt < 9; nt++)
#pragma unroll
        for (int r = 0; r < 4; r++) O[nt][r] = 0.f;
    float m0 = -1e30f, m1 = -1e30f;
    unsigned aQ[4][4];

    const int nch = KROWS / 128;
    for (int ch = 0; ch < nch; ch++) {
        int buf = ch & 1;
        if (ch + 1 < nch) { stage(ch + 1, buf ^ 1); CP_COMMIT(); CP_WAIT(1); }
        else CP_WAIT(0);
        __syncthreads();

        if (ch == 0) {
#pragma unroll
            for (int kc = 0; kc < 4; kc++)
                ldsm4(aQ[kc][0], aQ[kc][1], aQ[kc][2], aQ[kc][3],
                      suQ + ((qb + (lane & 15)) * 72 + kc * 16 + (lane >> 4) * 8) * 2);
        }

        unsigned bK = suK + buf * SKB * 2;
        const __half* sVb = sV + buf * SVB;

        float S[16][4];
#pragma unroll
        for (int np = 0; np < 8; np++) {
            S[2 * np][0] = S[2 * np][1] = S[2 * np][2] = S[2 * np][3] = 0.f;
            S[2 * np + 1][0] = S[2 * np + 1][1] = S[2 * np + 1][2] = S[2 * np + 1][3] = 0.f;
#pragma unroll
            for (int kc = 0; kc < 4; kc++) {
                unsigned b0, b1, b2, b3;
                ldsm4(b0, b1, b2, b3,
                      bK + ((np * 16 + (lane & 7) + (lane >> 4) * 8) * 72
                            + kc * 16 + ((lane >> 3) & 1) * 8) * 2);
                mma_f16(S[2 * np], aQ[kc], b0, b1);
                mma_f16(S[2 * np + 1], aQ[kc], b2, b3);
            }
        }

        if (ch == nch - 1) {
            int cb = ch * 128 + 2 * tg;
#pragma unroll
            for (int nt = 0; nt < 16; nt++) {
                int c = cb + nt * 8;
                if (c >= DD)     { S[nt][0] = -1e30f; S[nt][2] = -1e30f; }
                if (c + 1 >= DD) { S[nt][1] = -1e30f; S[nt][3] = -1e30f; }
            }
        }

        float rm0 = -1e30f, rm1 = -1e30f;
#pragma unroll
        for (int nt = 0; nt < 16; nt++) {
            rm0 = fmaxf(rm0, fmaxf(S[nt][0], S[nt][1]));
            rm1 = fmaxf(rm1, fmaxf(S[nt][2], S[nt][3]));
        }
        rm0 = fmaxf(rm0, __shfl_xor_sync(0xffffffffu, rm0, 1));
        rm0 = fmaxf(rm0, __shfl_xor_sync(0xffffffffu, rm0, 2));
        rm1 = fmaxf(rm1, __shfl_xor_sync(0xffffffffu, rm1, 1));
        rm1 = fmaxf(rm1, __shfl_xor_sync(0xffffffffu, rm1, 2));
        float mn0 = fmaxf(m0, rm0), mn1 = fmaxf(m1, rm1);
        float a0 = ex2f(m0 - mn0), a1 = ex2f(m1 - mn1);
        m0 = mn0; m1 = mn1;
#pragma unroll
        for (int nt = 0; nt < 9; nt++) {
            O[nt][0] *= a0; O[nt][1] *= a0;
            O[nt][2] *= a1; O[nt][3] *= a1;
        }

        unsigned pf[16][2];
#pragma unroll
        for (int nt = 0; nt < 16; nt++) {
            pf[nt][0] = exp2h2(S[nt][0] - m0, S[nt][1] - m0);
            pf[nt][1] = exp2h2(S[nt][2] - m1, S[nt][3] - m1);
        }

#pragma unroll
        for (int kc = 0; kc < 8; kc++) {
            unsigned A4[4] = {pf[2 * kc][0], pf[2 * kc][1], pf[2 * kc + 1][0], pf[2 * kc + 1][1]};
#pragma unroll
            for (int nt = 0; nt < 9; nt++) {
                const __half* vp = &sVb[(nt * 8 + grp) * 136 + kc * 16 + 2 * tg];
                unsigned b0 = *(const unsigned*)vp;
                unsigned b1 = *(const unsigned*)(vp + 8);
                mma_f16(O[nt], A4, b0, b1);
            }
        }
        __syncthreads();
    }

    float l0 = __shfl_sync(0xffffffffu, O[8][0], lane & ~3);
    float l1 = __shfl_sync(0xffffffffu, O[8][2], lane & ~3);
    float inv0 = 1.f / l0, inv1 = 1.f / l1;
#pragma unroll
    for (int nt = 0; nt < 8; nt++) {
        int c = nt * 8 + 2 * tg;
        *(__half2*)&g_at16[((size_t)head * HW + q0 + qb + grp) * 64 + c] =
            __floats2half2_rn(O[nt][0] * inv0, O[nt][1] * inv0);
        *(__half2*)&g_at16[((size_t)head * HW + q0 + qb + grp + 8) * 64 + c] =
            __floats2half2_rn(O[nt][2] * inv1, O[nt][3] * inv1);
    }
}

// ---------------- final: gate 1x1 via f16 mma + LSTM update (R10 version) ----------------
#define FA_HALVES (64 * 72)
#define FW_HALVES (256 * 72)
#define FG_OFF (FA_HALVES + FW_HALVES)
#define FINAL_SMEM (FG_OFF * 2 + 64 * 257 * 4)

__device__ __forceinline__ float tanh_fast(float x) {
    float e = __expf(-2.f * fabsf(x));
    float r = (1.f - e) / (1.f + e);
    return copysignf(r, x);
}

__global__ void __launch_bounds__(256) final_k(const float* __restrict__ c_in,
                                               const float* __restrict__ b_i,
                                               const float* __restrict__ b_f,
                                               const float* __restrict__ b_g,
                                               const float* __restrict__ b_o,
                                               float* __restrict__ out) {
    extern __shared__ __half smf[];
    unsigned suA = (unsigned)__cvta_generic_to_shared(smf);
    unsigned suW = suA + FA_HALVES * 2;
    float* s_gate = (float*)(smf + FG_OFF);

    int n = blockIdx.z, g = blockIdx.y, pxt = blockIdx.x;
    int pxbase = pxt * 64;
    int head = n * GG + g;
    int t = threadIdx.x, w = t >> 5, lane = t & 31;
    int grp = lane >> 2, tg = lane & 3;
    int pxg = w >> 1, nh = w & 1;

    for (int r = t; r < 512; r += 256) {
        int px = r >> 3, seg = r & 7;
        cp16(suA + (px * 72 + seg * 8) * 2,
             g_at16 + ((size_t)head * HW + pxbase + px) * 64 + seg * 8);
    }
    for (int r = t; r < 2048; r += 256) {
        int row = r >> 3, seg = r & 7;
        cp16(suW + (row * 72 + seg * 8) * 2,
             g_wa16 + ((size_t)((row >> 6) * GG + g) * 64 + (row & 63)) * 64 + seg * 8);
    }
    CP_COMMIT();
    CP_WAIT(0);
    __syncthreads();

    unsigned aA[4][4];
#pragma unroll
    for (int kc = 0; kc < 4; kc++)
        ldsm4(aA[kc][0], aA[kc][1], aA[kc][2], aA[kc][3],
              suA + ((pxg * 16 + (lane & 15)) * 72 + kc * 16 + (lane >> 4) * 8) * 2);

    float acc[16][4];
#pragma unroll
    for (int nt = 0; nt < 16; nt++) {
        acc[nt][0] = acc[nt][1] = acc[nt][2] = acc[nt][3] = 0.f;
#pragma unroll
        for (int kc = 0; kc < 4; kc++) {
            unsigned b0, b1;
            ldsm2(b0, b1, suW + ((nh * 128 + nt * 8 + (lane & 7)) * 72
                                 + kc * 16 + ((lane >> 3) & 1) * 8) * 2);
            mma_f16(acc[nt], aA[kc], b0, b1);
        }
    }

#pragma unroll
    for (int nt = 0; nt < 16; nt++) {
        int col = nh * 128 + nt * 8 + 2 * tg;
        int r0 = pxg * 16 + grp;
        s_gate[r0 * 257 + col]           = acc[nt][0];
        s_gate[r0 * 257 + col + 1]       = acc[nt][1];
        s_gate[(r0 + 8) * 257 + col]     = acc[nt][2];
        s_gate[(r0 + 8) * 257 + col + 1] = acc[nt][3];
    }
    __syncthreads();

    int pxl = t & 63, cb0 = t >> 6;
    int pxglob = pxbase + pxl;
#pragma unroll 4
    for (int k = 0; k < 16; k++) {
        int co = k * 4 + cb0;
        int ch = g * 64 + co;
        size_t gi = ((size_t)(n * 512 + ch)) * HW + pxglob;
        float ai = s_gate[pxl * 257 + co]       + b_i[ch] + g_gx[0][gi];
        float af = s_gate[pxl * 257 + 64 + co]  + b_f[ch] + g_gx[1][gi];
        float ag = s_gate[pxl * 257 + 128 + co] + b_g[ch] + g_gx[2][gi];
        float ao = s_gate[pxl * 257 + 192 + co] + b_o[ch] + g_gx[3][gi];
        float iv = 1.f / (1.f + __expf(-ai));
        float fv = 1.f / (1.f + __expf(-af));
        float gv = tanh_fast(ag);
        float ov = 1.f / (1.f + __expf(-ao));
        float cn = fv * c_in[gi] + iv * gv;
        out[gi] = ov * tanh_fast(cn);
    }
}

// ---------------- launch ----------------
extern "C" void kernel_launch(void* const* d_in, const int* in_sizes, int n_in,
                              void* d_out, int out_size) {
    const float* x_in = (const float*)d_in[0];
    const float* h    = (const float*)d_in[1];
    const float* c    = (const float*)d_in[2];
    const float* tau  = (const float*)d_in[3];
    const float* W_x  = (const float*)d_in[4];
    const float* W_ig = (const float*)d_in[5];
    const float* W_q  = (const float*)d_in[6];
    const float* W_k  = (const float*)d_in[7];
    const float* W_v  = (const float*)d_in[8];
    const float* Wi_a = (const float*)d_in[9];
    const float* Wi_x = (const float*)d_in[10];
    const float* b_i  = (const float*)d_in[11];
    const float* Wf_a = (const float*)d_in[12];
    const float* Wf_x = (const float*)d_in[13];
    const float* b_f  = (const float*)d_in[14];
    const float* Wg_a = (const float*)d_in[15];
    const float* Wg_x = (const float*)d_in[16];
    const float* b_g  = (const float*)d_in[17];
    const float* Wo_a = (const float*)d_in[18];
    const float* Wo_x = (const float*)d_in[19];
    const float* b_o  = (const float*)d_in[20];
    float* out = (float*)d_out;

    cudaFuncSetAttribute(attn_k, cudaFuncAttributeMaxDynamicSharedMemorySize, ATTN_SMEM);
    cudaFuncSetAttribute(conv3fused_k, cudaFuncAttributeMaxDynamicSharedMemorySize, CONV_SMEM);
    cudaFuncSetAttribute(final_k, cudaFuncAttributeMaxDynamicSharedMemorySize, FINAL_SMEM);

    prep_misc_k<<<dim3(1536, 3), 256>>>(W_x, W_ig, Wi_a, Wf_a, Wg_a, Wo_a);
    prep_wc_all_k<<<dim3((8 * 128 * 9 * 64 + 255) / 256, 7), 256>>>(W_q, W_k, W_v,
                                                                    Wi_x, Wf_x, Wg_x, Wo_x, tau);
    copy_merged_k<<<dim3(9, 9, NB), 256>>>(x_in, h);
    projmma_k<<<dim3(18, GG, NB), 256>>>();

    conv3fused_k<<<dim3(9, GG, NB), 256, CONV_SMEM>>>();   // all 7 convs, slot-paired

    attn_k<<<dim3(HW / 128, GG, NB), 256, ATTN_SMEM>>>();

    final_k<<<dim3(HW / 64, GG, NB), 256, FINAL_SMEM>>>(c, b_i, b_f, b_g, b_o, out);
}

// round 14
// speedup vs baseline: 1.1632x; 1.0756x over previous
#include <cuda_runtime.h>
#include <cuda_fp16.h>

// Problem constants
#define NB   2
#define GG   8
#define HW   2304     // 48*48
#define DD   2116     // 46*46
#define KROWS 2176    // DD padded to chunk multiple (17*128)
#define VROWS 2120    // DD padded for f16 16B alignment

// ---------------- scratch ----------------
__device__ __align__(256) __half g_xh16[NB][GG][HW][128];     // xh f16 [px][c]
__device__ __align__(256) __half g_in16[NB][HW][768];         // x_in+h f16 [px][c]
__device__ __align__(256) __half g_qt16[NB * GG * HW * 64];   // q [head][px][c] (tau*log2e folded)
__device__ __align__(256) __half g_kt16[NB * GG * KROWS * 64];// k [head][d][c]
__device__ __align__(256) __half g_vth[NB * GG * 64 * VROWS + 256]; // v [head][c][d]
__device__ __align__(256) __half g_at16[NB * GG * HW * 64];   // a [head][px][c]
__device__ float g_gx[4][NB * 512 * HW];                      // gate conv outputs f32 [c][px]
__device__ __align__(256) __half g_wproj16[512 * 768];        // [co][ci]
__device__ __align__(256) __half g_wc16[7][GG][8][9][64][16]; // conv weights f16
__device__ __align__(256) __half g_wa16[4 * GG * 64 * 64];    // [gate][g][co][ci]

// ---------------- asm helpers ----------------
__device__ __forceinline__ void mma_f16(float* d, const unsigned* a, unsigned b0, unsigned b1) {
    asm volatile(
        "mma.sync.aligned.m16n8k16.row.col.f32.f16.f16.f32 "
        "{%0,%1,%2,%3}, {%4,%5,%6,%7}, {%8,%9}, {%0,%1,%2,%3};"
        : "+f"(d[0]), "+f"(d[1]), "+f"(d[2]), "+f"(d[3])
        : "r"(a[0]), "r"(a[1]), "r"(a[2]), "r"(a[3]), "r"(b0), "r"(b1));
}
__device__ __forceinline__ void ldsm4(unsigned& r0, unsigned& r1, unsigned& r2, unsigned& r3,
                                      unsigned a) {
    asm volatile("ldmatrix.sync.aligned.m8n8.x4.shared.b16 {%0,%1,%2,%3}, [%4];"
                 : "=r"(r0), "=r"(r1), "=r"(r2), "=r"(r3) : "r"(a));
}
__device__ __forceinline__ void ldsm2(unsigned& r0, unsigned& r1, unsigned a) {
    asm volatile("ldmatrix.sync.aligned.m8n8.x2.shared.b16 {%0,%1}, [%2];"
                 : "=r"(r0), "=r"(r1) : "r"(a));
}
__device__ __forceinline__ unsigned exp2h2(float lo, float hi) {
    unsigned r;
    asm("{\n\t.reg .b32 t;\n\tcvt.rn.f16x2.f32 t, %2, %1;\n\tex2.approx.f16x2 %0, t;\n\t}"
        : "=r"(r) : "f"(lo), "f"(hi));
    return r;
}
__device__ __forceinline__ float ex2f(float x) {
    float y;
    asm("ex2.approx.ftz.f32 %0, %1;" : "=f"(y) : "f"(x));
    return y;
}
__device__ __forceinline__ void cp16(unsigned dst, const void* src) {
    asm volatile("cp.async.cg.shared.global [%0], [%1], 16;" :: "r"(dst), "l"(src));
}
__device__ __forceinline__ void cp16p(unsigned dst, const void* src, int sz) {
    asm volatile("cp.async.cg.shared.global [%0], [%1], 16, %2;" :: "r"(dst), "l"(src), "r"(sz));
}
#define CP_COMMIT() asm volatile("cp.async.commit_group;")
#define CP_WAIT(n)  asm volatile("cp.async.wait_group %0;" :: "n"(n))

// ---------------- merged misc prep + transposing copies (5 planes) ----------------
__global__ void prep_misc_k(const float* __restrict__ Wx, const float* __restrict__ Wig,
                            const float* __restrict__ Wi, const float* __restrict__ Wf,
                            const float* __restrict__ Wg, const float* __restrict__ Wo,
                            const float* __restrict__ x_in, const float* __restrict__ h) {
    int i = blockIdx.x * 256 + threadIdx.x;
    if (blockIdx.y == 0) {
        if (i >= 512 * 768) return;
        int co = i / 768, ci = i % 768;
        float v = (ci < 256) ? Wx[co * 256 + ci] : Wig[co * 512 + (ci - 256)];
        g_wproj16[i] = __float2half(v);
    } else if (blockIdx.y == 1) {
        const int nk = NB * GG * (KROWS - DD) * 64;
        if (i < nk) {
            int c = i & 63;
            int r = (i >> 6) % (KROWS - DD);
            int hd = i / ((KROWS - DD) * 64);
            g_kt16[((size_t)hd * KROWS + DD + r) * 64 + c] = __float2half(0.f);
        }
        const int nv = NB * GG * 64 * (VROWS - DD);
        if (i < nv) {
            int p = i % (VROWS - DD);
            int row = i / (VROWS - DD);
            g_vth[(size_t)row * VROWS + DD + p] = __float2half(0.f);
        }
        if (i < 256) g_vth[NB * GG * 64 * VROWS + i] = __float2half(0.f);
    } else if (blockIdx.y == 2) {
        if (i >= 4 * GG * 64 * 64) return;
        int ci = i & 63;
        int co = (i >> 6) & 63;
        int g  = (i >> 12) & 7;
        int slot = i >> 15;
        const float* W = (slot == 0) ? Wi : (slot == 1) ? Wf : (slot == 2) ? Wg : Wo;
        g_wa16[((slot * GG + g) * 64 + co) * 64 + ci] = __float2half(W[(g * 64 + co) * 64 + ci]);
    } else if (blockIdx.y == 3) {
        // h -> xh upper half (f16 [px][c])
        if (i >= NB * GG * HW) return;
        int px = i % HW;
        int g  = (i / HW) % GG;
        int n  = i / (GG * HW);
        __half2* dst = (__half2*)&g_xh16[n][g][px][64];
        const float* hb = h + ((size_t)n * 512 + g * 64) * HW + px;
#pragma unroll 8
        for (int c2 = 0; c2 < 32; c2++)
            dst[c2] = __floats2half2_rn(hb[(2 * c2) * HW], hb[(2 * c2 + 1) * HW]);
    } else {
        // x_in + h -> g_in16 [px][768]
        if (i >= NB * HW) return;
        int px = i % HW;
        int n  = i / HW;
        __half2* dst = (__half2*)&g_in16[n][px][0];
        const float* xb = x_in + (size_t)n * 256 * HW + px;
        const float* hb = h + (size_t)n * 512 * HW + px;
#pragma unroll 4
        for (int c2 = 0; c2 < 128; c2++)
            dst[c2] = __floats2half2_rn(xb[(2 * c2) * HW], xb[(2 * c2 + 1) * HW]);
#pragma unroll 4
        for (int c2 = 0; c2 < 256; c2++)
            dst[128 + c2] = __floats2half2_rn(hb[(2 * c2) * HW], hb[(2 * c2 + 1) * HW]);
    }
}

// coalesced-write weight transform: i maps (g, cb, tap, co, ci16) = g_wc16 linear order
__global__ void prep_wc_all_k(const float* __restrict__ Wq, const float* __restrict__ Wk,
                              const float* __restrict__ Wv, const float* __restrict__ Wi,
                              const float* __restrict__ Wf, const float* __restrict__ Wg,
                              const float* __restrict__ Wo, const float* __restrict__ tau) {
    int slot = blockIdx.y;
    const float* W;
    switch (slot) {
        case 0: W = Wq; break; case 1: W = Wk; break; case 2: W = Wv; break;
        case 3: W = Wi; break; case 4: W = Wf; break; case 5: W = Wg; break;
        default: W = Wo; break;
    }
    int i = blockIdx.x * 256 + threadIdx.x;
    if (i >= GG * 8 * 9 * 64 * 16) return;
    int ci16 = i & 15;
    int co   = (i >> 4) & 63;
    int tap  = (i >> 10) % 9;
    int cb   = (i / 9216) & 7;
    int g    = i / 73728;
    int ci   = cb * 16 + ci16;
    float v = W[((g * 64 + co) * 128 + ci) * 9 + tap];
    if (slot == 0) v *= tau[g] * 1.44269504f;
    (&g_wc16[0][0][0][0][0][0])[(size_t)slot * (GG * 73728) + i] = __float2half(v);
}

// ---------------- proj 1x1 via f16 mma (128 px/block, 32-ci chunks) ----------------
#define PJ_IP 40
#define PJI (128 * PJ_IP)   // 5120 halves
#define PJW (64 * PJ_IP)    // 2560 halves

__global__ void __launch_bounds__(256) projmma_k() {
    __shared__ __align__(16) __half spj[2 * PJI + 2 * PJW];
    int n = blockIdx.z, g = blockIdx.y, pxt = blockIdx.x;
    int pbase = pxt * 128;
    int t = threadIdx.x, w = t >> 5, lane = t & 31;
    int grp = lane >> 2, tg = lane & 3;

    unsigned suI = (unsigned)__cvta_generic_to_shared(spj);
    unsigned suW = suI + 2 * PJI * 2;

    float acc[8][4];
#pragma unroll
    for (int nt = 0; nt < 8; nt++)
#pragma unroll
        for (int r = 0; r < 4; r++) acc[nt][r] = 0.f;

    auto stage = [&](int it, int buf) {
        int cb = it * 32;
        for (int idx = t; idx < 512; idx += 256) {
            int px = idx >> 2, seg = idx & 3;
            cp16(suI + (buf * PJI + px * PJ_IP + seg * 8) * 2,
                 &g_in16[n][pbase + px][cb + seg * 8]);
        }
        {
            int co = t >> 2, seg = t & 3;
            if (co < 64)
                cp16(suW + (buf * PJW + co * PJ_IP + seg * 8) * 2,
                     g_wproj16 + (g * 64 + co) * 768 + cb + seg * 8);
        }
    };

    stage(0, 0);
    CP_COMMIT();
    for (int it = 0; it < 24; it++) {
        int buf = it & 1;
        if (it + 1 < 24) { stage(it + 1, buf ^ 1); CP_COMMIT(); CP_WAIT(1); }
        else CP_WAIT(0);
        __syncthreads();
        unsigned bI = suI + buf * PJI * 2;
        unsigned bW = suW + buf * PJW * 2;
#pragma unroll
        for (int kc = 0; kc < 2; kc++) {
            unsigned a[4];
            ldsm4(a[0], a[1], a[2], a[3],
                  bI + ((w * 16 + (lane & 15)) * PJ_IP + kc * 16 + (lane >> 4) * 8) * 2);
#pragma unroll
            for (int nt = 0; nt < 8; nt++) {
                unsigned b0, b1;
                ldsm2(b0, b1, bW + ((nt * 8 + (lane & 7)) * PJ_IP + kc * 16
                                    + ((lane >> 3) & 1) * 8) * 2);
                mma_f16(acc[nt], a, b0, b1);
            }
        }
        __syncthreads();
    }

    __half* xb = &g_xh16[n][g][0][0];
    int px0 = pbase + w * 16 + grp;
#pragma unroll
    for (int nt = 0; nt < 8; nt++) {
        int co = nt * 8 + 2 * tg;
        *(__half2*)&xb[(size_t)px0 * 128 + co]       = __floats2half2_rn(acc[nt][0], acc[nt][1]);
        *(__half2*)&xb[(size_t)(px0 + 8) * 128 + co] = __floats2half2_rn(acc[nt][2], acc[nt][3]);
    }
}

// ---------------- fused grouped 3x3 convs: 512 threads, 32-ci weight chunks (R10) ----------------
#define CIN_PITCH 136
#define CIN_BUF (361 * CIN_PITCH)      // 49096 halves = 98192 B
#define CW_PITCH 24
#define CW_BUF (1152 * CW_PITCH)       // 27648 halves = 55296 B per buffer
#define CONV_SMEM ((CIN_BUF + 2 * CW_BUF) * 2)   // 208,784 B

__global__ void __launch_bounds__(512) conv3fused_k() {
    extern __shared__ __half smc[];
    unsigned su_in = (unsigned)__cvta_generic_to_shared(smc);
    unsigned su_w  = su_in + CIN_BUF * 2;

    int g = blockIdx.y, n = blockIdx.z;
    int ty0 = (blockIdx.x / 3) * 16, tx0 = (blockIdx.x % 3) * 16;
    int t = threadIdx.x, w = t >> 5, lane = t & 31;
    int pxg = w & 7, cog = w >> 3;   // 8 row-groups of 2 rows, 2 co-halves
    int grp = lane >> 2, tg = lane & 3;
    int hbase = n * GG + g;

    const __half* xb = &g_xh16[n][g][0][0];

    // stage full input halo tile once: 19x19 px x 128 ci
    for (int idx = t; idx < 361 * 16; idx += 512) {
        int row = idx >> 4, seg = idx & 15;
        int y = row / 19, x = row - y * 19;
        int iy = ty0 - 1 + y, ix = tx0 - 1 + x;
        bool ok = ((unsigned)iy < 48u) && ((unsigned)ix < 48u);
        const __half* src = xb + (size_t)(ok ? iy * 48 + ix : 0) * 128 + seg * 8;
        cp16p(su_in + (row * CIN_PITCH + seg * 8) * 2, src, ok ? 16 : 0);
    }
    CP_COMMIT();

    // weight staging: s in 0..27, slot = s>>2, quarter = s&3 covers 32 ci (2x16 chunks)
    auto stageW = [&](int s, int buf) {
        int slot = s >> 2, q4 = s & 3;
        const __half* wb = &g_wc16[slot][g][0][0][0][0];
        for (int r = t; r < 1152; r += 512) {
            int it2 = r / 576, rem = r - it2 * 576;
            const __half* src = wb + (size_t)(q4 * 2 + it2) * 9216 + rem * 16;
            unsigned d = su_w + (buf * CW_BUF + r * CW_PITCH) * 2;
            cp16(d, src);
            cp16(d + 16, src + 8);
        }
    };

    stageW(0, 0);
    CP_COMMIT();

    float acc[2][4][4];
#pragma unroll
    for (int m = 0; m < 2; m++)
#pragma unroll
        for (int nt = 0; nt < 4; nt++)
#pragma unroll
            for (int r = 0; r < 4; r++) acc[m][nt][r] = 0.f;

    for (int s = 0; s < 28; s++) {
        int buf = s & 1;
        int slot = s >> 2, q4 = s & 3;
        if (s + 1 < 28) { stageW(s + 1, buf ^ 1); CP_COMMIT(); CP_WAIT(1); }
        else CP_WAIT(0);
        __syncthreads();

        int off = (slot == 1 || slot == 2) ? 1 : 0;   // k,v are pad=0
        unsigned bw = su_w + buf * CW_BUF * 2;

#pragma unroll
        for (int it2 = 0; it2 < 2; it2++) {
            int cioff = (q4 * 2 + it2) * 16;
#pragma unroll
            for (int kh = 0; kh < 3; kh++) {
#pragma unroll
                for (int kw = 0; kw < 3; kw++) {
                    unsigned b[4][2];
#pragma unroll
                    for (int nt = 0; nt < 4; nt++) {
                        unsigned addr = bw + ((it2 * 576 + (kh * 3 + kw) * 64 + cog * 32
                                               + nt * 8 + (lane & 7)) * CW_PITCH
                                              + ((lane >> 3) & 1) * 8) * 2;
                        ldsm2(b[nt][0], b[nt][1], addr);
                    }
#pragma unroll
                    for (int m = 0; m < 2; m++) {
                        int row = (pxg * 2 + m + kh + off) * 19 + (lane & 15) + kw + off;
                        unsigned a[4];
                        ldsm4(a[0], a[1], a[2], a[3],
                              su_in + (row * CIN_PITCH + cioff + (lane >> 4) * 8) * 2);
#pragma unroll
                        for (int nt = 0; nt < 4; nt++)
                            mma_f16(acc[m][nt], a, b[nt][0], b[nt][1]);
                    }
                }
            }
        }
        __syncthreads();

        if (q4 == 3) {   // slot complete: write out, reset acc
#pragma unroll
            for (int m = 0; m < 2; m++) {
                int y = ty0 + pxg * 2 + m;
#pragma unroll
                for (int nt = 0; nt < 4; nt++) {
                    int co = cog * 32 + nt * 8 + 2 * tg;
                    int x1 = tx0 + grp, x2 = x1 + 8;
                    if (slot == 1) {          // K f16 [d][c]
                        if (y < 46) {
                            if (x1 < 46)
                                *(__half2*)&g_kt16[((size_t)hbase * KROWS + y * 46 + x1) * 64 + co] =
                                    __floats2half2_rn(acc[m][nt][0], acc[m][nt][1]);
                            if (x2 < 46)
                                *(__half2*)&g_kt16[((size_t)hbase * KROWS + y * 46 + x2) * 64 + co] =
                                    __floats2half2_rn(acc[m][nt][2], acc[m][nt][3]);
                        }
                    } else if (slot == 2) {   // V f16 [c][d]
                        if (y < 46) {
                            if (x1 < 46) {
                                int d = y * 46 + x1;
                                g_vth[(size_t)(hbase * 64 + co) * VROWS + d] = __float2half(acc[m][nt][0]);
                                g_vth[(size_t)(hbase * 64 + co + 1) * VROWS + d] = __float2half(acc[m][nt][1]);
                            }
                            if (x2 < 46) {
                                int d = y * 46 + x2;
                                g_vth[(size_t)(hbase * 64 + co) * VROWS + d] = __float2half(acc[m][nt][2]);
                                g_vth[(size_t)(hbase * 64 + co + 1) * VROWS + d] = __float2half(acc[m][nt][3]);
                            }
                        }
                    } else if (slot == 0) {   // Q f16 [px][c]
                        *(__half2*)&g_qt16[((size_t)hbase * HW + y * 48 + x1) * 64 + co] =
                            __floats2half2_rn(acc[m][nt][0], acc[m][nt][1]);
                        *(__half2*)&g_qt16[((size_t)hbase * HW + y * 48 + x2) * 64 + co] =
                            __floats2half2_rn(acc[m][nt][2], acc[m][nt][3]);
                    } else {                  // gates f32 [c][px]
                        float* ob = &g_gx[slot - 3][0] + (size_t)hbase * 64 * HW + y * 48;
                        ob[co * HW + x1] = acc[m][nt][0];
                        ob[(co + 1) * HW + x1] = acc[m][nt][1];
                        ob[co * HW + x2] = acc[m][nt][2];
                        ob[(co + 1) * HW + x2] = acc[m][nt][3];
                    }
                }
            }
#pragma unroll
            for (int m = 0; m < 2; m++)
#pragma unroll
                for (int nt = 0; nt < 4; nt++)
#pragma unroll
                    for (int r = 0; r < 4; r++) acc[m][nt][r] = 0.f;
        }
    }
}

// ---------------- flash attention: all-f16 mma (unchanged) ----------------
#define SQB 9216
#define SKB 9216
#define SVB 9792
#define ATTN_SMEM ((SQB + 2 * SKB + 2 * SVB) * 2)

__global__ void __launch_bounds__(256) attn_k() {
    extern __shared__ __half sma[];
    __half* sQ = sma;
    __half* sK = sma + SQB;
    __half* sV = sK + 2 * SKB;

    int n = blockIdx.z, g = blockIdx.y;
    int head = n * GG + g;
    int q0 = blockIdx.x * 128;
    int t = threadIdx.x, w = t >> 5, lane = t & 31;
    int grp = lane >> 2, tg = lane & 3;
    int qb = w * 16;

    unsigned suQ = (unsigned)__cvta_generic_to_shared(sQ);
    unsigned suK = (unsigned)__cvta_generic_to_shared(sK);
    unsigned suV = (unsigned)__cvta_generic_to_shared(sV);

    for (int idx = t; idx < 1024; idx += 256) {
        int q = idx >> 3, seg = idx & 7;
        cp16(suQ + (q * 72 + seg * 8) * 2,
             g_qt16 + ((size_t)head * HW + q0 + q) * 64 + seg * 8);
    }
    for (int idx = t; idx < 2 * 8 * 136; idx += 256) {
        int buf = idx / (8 * 136);
        int r = idx % (8 * 136);
        int row = 64 + r / 136, col = r % 136;
        sV[buf * SVB + row * 136 + col] = __float2half(row == 64 ? 1.f : 0.f);
    }

    auto stage = [&](int ch, int buf) {
        int db = ch * 128;
        const __half* ksrc = g_kt16 + ((size_t)head * KROWS + db) * 64;
        for (int idx = t; idx < 1024; idx += 256) {
            int d = idx >> 3, seg = idx & 7;
            cp16(suK + (buf * SKB + d * 72 + seg * 8) * 2, ksrc + d * 64 + seg * 8);
        }
        const __half* vsrc = g_vth + (size_t)head * 64 * VROWS + db;
        for (int idx = t; idx < 1024; idx += 256) {
            int c = idx >> 4, seg = idx & 15;
            cp16(suV + (buf * SVB + c * 136 + seg * 8) * 2, vsrc + (size_t)c * VROWS + seg * 8);
        }
    };

    stage(0, 0);
    CP_COMMIT();

    float O[9][4];
#pragma unroll
    for (int nt = 0; nt < 9; nt++)
#pragma unroll
        for (int r = 0; r < 4; r++) O[nt][r] = 0.f;
    float m0 = -1e30f, m1 = -1e30f;
    unsigned aQ[4][4];

    const int nch = KROWS / 128;
    for (int ch = 0; ch < nch; ch++) {
        int buf = ch & 1;
        if (ch + 1 < nch) { stage(ch + 1, buf ^ 1); CP_COMMIT(); CP_WAIT(1); }
        else CP_WAIT(0);
        __syncthreads();

        if (ch == 0) {
#pragma unroll
            for (int kc = 0; kc < 4; kc++)
                ldsm4(aQ[kc][0], aQ[kc][1], aQ[kc][2], aQ[kc][3],
                      suQ + ((qb + (lane & 15)) * 72 + kc * 16 + (lane >> 4) * 8) * 2);
        }

        unsigned bK = suK + buf * SKB * 2;
        const __half* sVb = sV + buf * SVB;

        float S[16][4];
#pragma unroll
        for (int np = 0; np < 8; np++) {
            S[2 * np][0] = S[2 * np][1] = S[2 * np][2] = S[2 * np][3] = 0.f;
            S[2 * np + 1][0] = S[2 * np + 1][1] = S[2 * np + 1][2] = S[2 * np + 1][3] = 0.f;
#pragma unroll
            for (int kc = 0; kc < 4; kc++) {
                unsigned b0, b1, b2, b3;
                ldsm4(b0, b1, b2, b3,
                      bK + ((np * 16 + (lane & 7) + (lane >> 4) * 8) * 72
                            + kc * 16 + ((lane >> 3) & 1) * 8) * 2);
                mma_f16(S[2 * np], aQ[kc], b0, b1);
                mma_f16(S[2 * np + 1], aQ[kc], b2, b3);
            }
        }

        if (ch == nch - 1) {
            int cb = ch * 128 + 2 * tg;
#pragma unroll
            for (int nt = 0; nt < 16; nt++) {
                int c = cb + nt * 8;
                if (c >= DD)     { S[nt][0] = -1e30f; S[nt][2] = -1e30f; }
                if (c + 1 >= DD) { S[nt][1] = -1e30f; S[nt][3] = -1e30f; }
            }
        }

        float rm0 = -1e30f, rm1 = -1e30f;
#pragma unroll
        for (int nt = 0; nt < 16; nt++) {
            rm0 = fmaxf(rm0, fmaxf(S[nt][0], S[nt][1]));
            rm1 = fmaxf(rm1, fmaxf(S[nt][2], S[nt][3]));
        }
        rm0 = fmaxf(rm0, __shfl_xor_sync(0xffffffffu, rm0, 1));
        rm0 = fmaxf(rm0, __shfl_xor_sync(0xffffffffu, rm0, 2));
        rm1 = fmaxf(rm1, __shfl_xor_sync(0xffffffffu, rm1, 1));
        rm1 = fmaxf(rm1, __shfl_xor_sync(0xffffffffu, rm1, 2));
        float mn0 = fmaxf(m0, rm0), mn1 = fmaxf(m1, rm1);
        float a0 = ex2f(m0 - mn0), a1 = ex2f(m1 - mn1);
        m0 = mn0; m1 = mn1;
#pragma unroll
        for (int nt = 0; nt < 9; nt++) {
            O[nt][0] *= a0; O[nt][1] *= a0;
            O[nt][2] *= a1; O[nt][3] *= a1;
        }

        unsigned pf[16][2];
#pragma unroll
        for (int nt = 0; nt < 16; nt++) {
            pf[nt][0] = exp2h2(S[nt][0] - m0, S[nt][1] - m0);
            pf[nt][1] = exp2h2(S[nt][2] - m1, S[nt][3] - m1);
        }

#pragma unroll
        for (int kc = 0; kc < 8; kc++) {
            unsigned A4[4] = {pf[2 * kc][0], pf[2 * kc][1], pf[2 * kc + 1][0], pf[2 * kc + 1][1]};
#pragma unroll
            for (int nt = 0; nt < 9; nt++) {
                const __half* vp = &sVb[(nt * 8 + grp) * 136 + kc * 16 + 2 * tg];
                unsigned b0 = *(const unsigned*)vp;
                unsigned b1 = *(const unsigned*)(vp + 8);
                mma_f16(O[nt], A4, b0, b1);
            }
        }
        __syncthreads();
    }

    float l0 = __shfl_sync(0xffffffffu, O[8][0], lane & ~3);
    float l1 = __shfl_sync(0xffffffffu, O[8][2], lane & ~3);
    float inv0 = 1.f / l0, inv1 = 1.f / l1;
#pragma unroll
    for (int nt = 0; nt < 8; nt++) {
        int c = nt * 8 + 2 * tg;
        *(__half2*)&g_at16[((size_t)head * HW + q0 + qb + grp) * 64 + c] =
            __floats2half2_rn(O[nt][0] * inv0, O[nt][1] * inv0);
        *(__half2*)&g_at16[((size_t)head * HW + q0 + qb + grp + 8) * 64 + c] =
            __floats2half2_rn(O[nt][2] * inv1, O[nt][3] * inv1);
    }
}

// ---------------- final: gate 1x1 via f16 mma + LSTM update (unchanged) ----------------
#define FA_HALVES (64 * 72)
#define FW_HALVES (256 * 72)
#define FG_OFF (FA_HALVES + FW_HALVES)
#define FINAL_SMEM (FG_OFF * 2 + 64 * 257 * 4)

__device__ __forceinline__ float tanh_fast(float x) {
    float e = __expf(-2.f * fabsf(x));
    float r = (1.f - e) / (1.f + e);
    return copysignf(r, x);
}

__global__ void __launch_bounds__(256) final_k(const float* __restrict__ c_in,
                                               const float* __restrict__ b_i,
                                               const float* __restrict__ b_f,
                                               const float* __restrict__ b_g,
                                               const float* __restrict__ b_o,
                                               float* __restrict__ out) {
    extern __shared__ __half smf[];
    unsigned suA = (unsigned)__cvta_generic_to_shared(smf);
    unsigned suW = suA + FA_HALVES * 2;
    float* s_gate = (float*)(smf + FG_OFF);

    int n = blockIdx.z, g = blockIdx.y, pxt = blockIdx.x;
    int pxbase = pxt * 64;
    int head = n * GG + g;
    int t = threadIdx.x, w = t >> 5, lane = t & 31;
    int grp = lane >> 2, tg = lane & 3;
    int pxg = w >> 1, nh = w & 1;

    for (int r = t; r < 512; r += 256) {
        int px = r >> 3, seg = r & 7;
        cp16(suA + (px * 72 + seg * 8) * 2,
             g_at16 + ((size_t)head * HW + pxbase + px) * 64 + seg * 8);
    }
    for (int r = t; r < 2048; r += 256) {
        int row = r >> 3, seg = r & 7;
        cp16(suW + (row * 72 + seg * 8) * 2,
             g_wa16 + ((size_t)((row >> 6) * GG + g) * 64 + (row & 63)) * 64 + seg * 8);
    }
    CP_COMMIT();
    CP_WAIT(0);
    __syncthreads();

    unsigned aA[4][4];
#pragma unroll
    for (int kc = 0; kc < 4; kc++)
        ldsm4(aA[kc][0], aA[kc][1], aA[kc][2], aA[kc][3],
              suA + ((pxg * 16 + (lane & 15)) * 72 + kc * 16 + (lane >> 4) * 8) * 2);

    float acc[16][4];
#pragma unroll
    for (int nt = 0; nt < 16; nt++) {
        acc[nt][0] = acc[nt][1] = acc[nt][2] = acc[nt][3] = 0.f;
#pragma unroll
        for (int kc = 0; kc < 4; kc++) {
            unsigned b0, b1;
            ldsm2(b0, b1, suW + ((nh * 128 + nt * 8 + (lane & 7)) * 72
                                 + kc * 16 + ((lane >> 3) & 1) * 8) * 2);
            mma_f16(acc[nt], aA[kc], b0, b1);
        }
    }

#pragma unroll
    for (int nt = 0; nt < 16; nt++) {
        int col = nh * 128 + nt * 8 + 2 * tg;
        int r0 = pxg * 16 + grp;
        s_gate[r0 * 257 + col]           = acc[nt][0];
        s_gate[r0 * 257 + col + 1]       = acc[nt][1];
        s_gate[(r0 + 8) * 257 + col]     = acc[nt][2];
        s_gate[(r0 + 8) * 257 + col + 1] = acc[nt][3];
    }
    __syncthreads();

    int pxl = t & 63, cb0 = t >> 6;
    int pxglob = pxbase + pxl;
#pragma unroll 4
    for (int k = 0; k < 16; k++) {
        int co = k * 4 + cb0;
        int ch = g * 64 + co;
        size_t gi = ((size_t)(n * 512 + ch)) * HW + pxglob;
        float ai = s_gate[pxl * 257 + co]       + b_i[ch] + g_gx[0][gi];
        float af = s_gate[pxl * 257 + 64 + co]  + b_f[ch] + g_gx[1][gi];
        float ag = s_gate[pxl * 257 + 128 + co] + b_g[ch] + g_gx[2][gi];
        float ao = s_gate[pxl * 257 + 192 + co] + b_o[ch] + g_gx[3][gi];
        float iv = 1.f / (1.f + __expf(-ai));
        float fv = 1.f / (1.f + __expf(-af));
        float gv = tanh_fast(ag);
        float ov = 1.f / (1.f + __expf(-ao));
        float cn = fv * c_in[gi] + iv * gv;
        out[gi] = ov * tanh_fast(cn);
    }
}

// ---------------- launch ----------------
extern "C" void kernel_launch(void* const* d_in, const int* in_sizes, int n_in,
                              void* d_out, int out_size) {
    const float* x_in = (const float*)d_in[0];
    const float* h    = (const float*)d_in[1];
    const float* c    = (const float*)d_in[2];
    const float* tau  = (const float*)d_in[3];
    const float* W_x  = (const float*)d_in[4];
    const float* W_ig = (const float*)d_in[5];
    const float* W_q  = (const float*)d_in[6];
    const float* W_k  = (const float*)d_in[7];
    const float* W_v  = (const float*)d_in[8];
    const float* Wi_a = (const float*)d_in[9];
    const float* Wi_x = (const float*)d_in[10];
    const float* b_i  = (const float*)d_in[11];
    const float* Wf_a = (const float*)d_in[12];
    const float* Wf_x = (const float*)d_in[13];
    const float* b_f  = (const float*)d_in[14];
    const float* Wg_a = (const float*)d_in[15];
    const float* Wg_x = (const float*)d_in[16];
    const float* b_g  = (const float*)d_in[17];
    const float* Wo_a = (const float*)d_in[18];
    const float* Wo_x = (const float*)d_in[19];
    const float* b_o  = (const float*)d_in[20];
    float* out = (float*)d_out;

    cudaFuncSetAttribute(attn_k, cudaFuncAttributeMaxDynamicSharedMemorySize, ATTN_SMEM);
    cudaFuncSetAttribute(conv3fused_k, cudaFuncAttributeMaxDynamicSharedMemorySize, CONV_SMEM);
    cudaFuncSetAttribute(final_k, cudaFuncAttributeMaxDynamicSharedMemorySize, FINAL_SMEM);

    prep_misc_k<<<dim3(1536, 5), 256>>>(W_x, W_ig, Wi_a, Wf_a, Wg_a, Wo_a, x_in, h);
    prep_wc_all_k<<<dim3((GG * 8 * 9 * 64 * 16 + 255) / 256, 7), 256>>>(W_q, W_k, W_v,
                                                                        Wi_x, Wf_x, Wg_x, Wo_x, tau);
    projmma_k<<<dim3(18, GG, NB), 256>>>();

    conv3fused_k<<<dim3(9, GG, NB), 512, CONV_SMEM>>>();   // all 7 convs, one wave

    attn_k<<<dim3(HW / 128, GG, NB), 256, ATTN_SMEM>>>();

    final_k<<<dim3(HW / 64, GG, NB), 256, FINAL_SMEM>>>(c, b_i, b_f, b_g, b_o, out);
}